// round 17
// baseline (speedup 1.0000x reference)
#include <cuda_runtime.h>
#include <cuda_bf16.h>
#include <math.h>

// NNUE HalfKA inference, two-phase, int8 table + s16 multipliers + DP2A + PDL:
//  Phase 1 (warp-per-row): comb = W_ft[f] + W_fft[f % 768];
//           s[f] = maxabs/127; q[f] = rint(comb/s) int8  (48 MB, L2-resident)
//  Phase 2: per batch element: a_f = v_f * s[feat_f]; T = max|a|;
//           u16_f = rint(a_f * 32767 / T); acc_d = sum_f q[f,d]*u16_f (dp2a);
//           hidden = bias + (T/32767)*acc; clip; output dot; sigmoid.
//  Gather loop uses the R11 shape (4 loads/iter, occ cap 10) — measured fastest
//  (47.4us); the R12 8-load superchunk batching regressed it (+3us, cross-CTA
//  L1tex queue spread). PDL retained (~2us: gather prologue overlaps build tail).

#define FT_OUT   1024
#define FPP      32
#define NVFEAT   768
#define NFEAT    49152
#define BLD_THREADS 256           // 8 warps = 8 rows per block
#define GTH_THREADS 128           // 128 threads * 8 dims (8 B int8) = one row

// 48 MB quantized combined table + per-row scales (static device scratch)
__device__ __align__(16) signed char g_qtab[(size_t)NFEAT * FT_OUT];
__device__ float g_scale[NFEAT];

__device__ __forceinline__ int dp2a_lo(unsigned a16, unsigned b8, int c) {
    int d;
    asm("dp2a.lo.s32.s32 %0, %1, %2, %3;" : "=r"(d) : "r"(a16), "r"(b8), "r"(c));
    return d;
}
__device__ __forceinline__ int dp2a_hi(unsigned a16, unsigned b8, int c) {
    int d;
    asm("dp2a.hi.s32.s32 %0, %1, %2, %3;" : "=r"(d) : "r"(a16), "r"(b8), "r"(c));
    return d;
}

// ---------------- Phase 1: build quantized table, one warp per row ----------------
__global__ __launch_bounds__(BLD_THREADS, 4)
void build_comb_kernel(const float* __restrict__ W_ft,
                       const float* __restrict__ W_fft)
{
    const int wid  = threadIdx.x >> 5;
    const int lane = threadIdx.x & 31;
    const int f    = blockIdx.x * 8 + wid;          // NFEAT/8 blocks

    const float4* wrow = (const float4*)(W_ft  + (size_t)f * FT_OUT);
    const float4* vrow = (const float4*)(W_fft + (size_t)(f % NVFEAT) * FT_OUT);

    // 1024 floats / warp: each lane 8 float4 chunks (coalesced per chunk)
    float4 w[8];
    #pragma unroll
    for (int k = 0; k < 8; k++) {
        float4 a = __ldcs(wrow + k * 32 + lane);    // stream W_ft, evict-first
        float4 v = __ldg (vrow + k * 32 + lane);
        w[k] = make_float4(a.x + v.x, a.y + v.y, a.z + v.z, a.w + v.w);
    }

    float m = 0.f;
    #pragma unroll
    for (int k = 0; k < 8; k++)
        m = fmaxf(m, fmaxf(fmaxf(fabsf(w[k].x), fabsf(w[k].y)),
                           fmaxf(fabsf(w[k].z), fabsf(w[k].w))));
    #pragma unroll
    for (int off = 16; off > 0; off >>= 1)
        m = fmaxf(m, __shfl_xor_sync(0xffffffffu, m, off));
    m = fmaxf(m, 1e-30f);
    if (lane == 0) g_scale[f] = m * (1.0f / 127.0f);
    const float inv = 127.0f / m;

    // PDL: allow dependent (gather) grid to start launching; its pre-wait
    // prologue overlaps our remaining stores. The dependent's
    // griddepcontrol.wait (full-grid completion) provides memory safety.
    asm volatile("griddepcontrol.launch_dependents;");

    char4* qrow = (char4*)(g_qtab + (size_t)f * FT_OUT);
    #pragma unroll
    for (int k = 0; k < 8; k++) {
        char4 q;
        q.x = (signed char)__float2int_rn(w[k].x * inv);
        q.y = (signed char)__float2int_rn(w[k].y * inv);
        q.z = (signed char)__float2int_rn(w[k].z * inv);
        q.w = (signed char)__float2int_rn(w[k].w * inv);
        qrow[k * 32 + lane] = q;
    }
}

// process one side's 2-feature chunk: PRMT transpose + 8 dp2a into acc[8]
__device__ __forceinline__ void dp2a_chunk(const uint2& q0, const uint2& q1,
                                           unsigned u, int* acc) {
    unsigned t, tb;
    t  = __byte_perm(q0.x, q1.x, 0x5140);
    tb = __byte_perm(q0.x, q1.x, 0x7362);
    acc[0] = dp2a_lo(u, t,  acc[0]);
    acc[1] = dp2a_hi(u, t,  acc[1]);
    acc[2] = dp2a_lo(u, tb, acc[2]);
    acc[3] = dp2a_hi(u, tb, acc[3]);
    t  = __byte_perm(q0.y, q1.y, 0x5140);
    tb = __byte_perm(q0.y, q1.y, 0x7362);
    acc[4] = dp2a_lo(u, t,  acc[4]);
    acc[5] = dp2a_hi(u, t,  acc[5]);
    acc[6] = dp2a_lo(u, tb, acc[6]);
    acc[7] = dp2a_hi(u, tb, acc[7]);
}

// ---------------- Phase 2: gather + dp2a accumulate + epilogue ----------------
__global__ __launch_bounds__(GTH_THREADS, 10)
void nnue_gather_kernel(
    const float* __restrict__ values,     // [NNZ]
    const int*   __restrict__ stm_feat,   // [NNZ]
    const int*   __restrict__ nstm_feat,  // [NNZ]
    const float* __restrict__ b_ft,       // [1024]
    const float* __restrict__ b_fft,      // [1024]
    const float* __restrict__ W_out,      // [2048]
    const float* __restrict__ b_out,      // [1]
    float*       __restrict__ out)        // [B]
{
    __shared__ __align__(16) int s_off[2 * FPP];  // byte offsets; [0,32)=stm, [32,64)=nstm
    __shared__ float    s_v[FPP];                 // raw values
    __shared__ float    s_a[2 * FPP];             // a_f = v * row_scale
    __shared__ unsigned s_u16[2 * (FPP / 2)];     // packed s16x2; [0,16)=stm, [16,32)=nstm
    __shared__ float    s_Tf;
    __shared__ float    s_red[GTH_THREADS / 32];

    const int b   = blockIdx.x;
    const int tid = threadIdx.x;

    int fs = 0, fn = 0;
    // ---- build-independent prologue (overlaps build tail under PDL) ----
    if (tid < FPP) {
        fs = stm_feat[b * FPP + tid];
        fn = nstm_feat[b * FPP + tid];
        s_v[tid]         = values[b * FPP + tid];
        s_off[tid]       = fs << 10;              // *1024 B/row
        s_off[FPP + tid] = fn << 10;
    }

    // ---- wait for build grid completion before touching table / scales ----
    asm volatile("griddepcontrol.wait;" ::: "memory");

    if (tid < FPP) {
        const float v = s_v[tid];
        s_a[tid]       = v * __ldg(g_scale + fs);
        s_a[FPP + tid] = v * __ldg(g_scale + fn);
    }
    __syncthreads();

    // warp 0: block max |a|, then pack s16 multipliers (one chunk of 2 feats per lane)
    if (tid < 32) {
        float m = fmaxf(fabsf(s_a[tid]), fabsf(s_a[tid + 32]));
        #pragma unroll
        for (int off = 16; off > 0; off >>= 1)
            m = fmaxf(m, __shfl_xor_sync(0xffffffffu, m, off));
        const float T = fmaxf(m, 1e-30f);
        const float invT = 32767.0f / T;
        if (tid == 0) s_Tf = T * (1.0f / 32767.0f);

        const int side = tid >> 4;                 // 0: stm chunks, 1: nstm chunks
        const int c    = tid & 15;
        const int base = side * FPP + 2 * c;
        const int u0 = __float2int_rn(s_a[base]     * invT);
        const int u1 = __float2int_rn(s_a[base + 1] * invT);
        s_u16[tid] = (unsigned)(u0 & 0xFFFF) | ((unsigned)u1 << 16);
    }
    __syncthreads();

    const char* base = (const char*)g_qtab + tid * 8;   // this thread's 8 dims

    int accs[8] = {0,0,0,0,0,0,0,0};
    int accn[8] = {0,0,0,0,0,0,0,0};

    // 16 chunks; each: 2 stm feats + 2 nstm feats (4 independent 8B loads)
    // (R11 shape — measured fastest; deeper batching regresses via L1tex-queue spread)
    #pragma unroll 4
    for (int c = 0; c < FPP / 2; c++) {
        const int2 offs = *(const int2*)&s_off[2 * c];
        const int2 offn = *(const int2*)&s_off[FPP + 2 * c];
        const unsigned us = s_u16[c];
        const unsigned un = s_u16[16 + c];

        const uint2 q0 = __ldcg((const uint2*)(base + offs.x));
        const uint2 q1 = __ldcg((const uint2*)(base + offs.y));
        const uint2 r0 = __ldcg((const uint2*)(base + offn.x));
        const uint2 r1 = __ldcg((const uint2*)(base + offn.y));

        dp2a_chunk(q0, q1, us, accs);
        dp2a_chunk(r0, r1, un, accn);
    }

    // epilogue: hidden = bias + Tf*acc; clip; partial output dot
    const float Tf = s_Tf;
    const int d = tid * 8;
    float p = 0.f;
    {
        float4 bf0 = *(const float4*)(b_ft  + d);
        float4 bf1 = *(const float4*)(b_ft  + d + 4);
        float4 bb0 = *(const float4*)(b_fft + d);
        float4 bb1 = *(const float4*)(b_fft + d + 4);
        float bias[8] = {bf0.x + bb0.x, bf0.y + bb0.y, bf0.z + bb0.z, bf0.w + bb0.w,
                         bf1.x + bb1.x, bf1.y + bb1.y, bf1.z + bb1.z, bf1.w + bb1.w};

        float4 ws0 = *(const float4*)(W_out + d);
        float4 ws1 = *(const float4*)(W_out + d + 4);
        float4 wn0 = *(const float4*)(W_out + FT_OUT + d);
        float4 wn1 = *(const float4*)(W_out + FT_OUT + d + 4);
        float ws[8] = {ws0.x, ws0.y, ws0.z, ws0.w, ws1.x, ws1.y, ws1.z, ws1.w};
        float wn[8] = {wn0.x, wn0.y, wn0.z, wn0.w, wn1.x, wn1.y, wn1.z, wn1.w};

        #pragma unroll
        for (int j = 0; j < 8; j++) {
            float hs = fmaf((float)accs[j], Tf, bias[j]);
            float hn = fmaf((float)accn[j], Tf, bias[j]);
            p = fmaf(fminf(fmaxf(hs, 0.f), 1.f), ws[j], p);
            p = fmaf(fminf(fmaxf(hn, 0.f), 1.f), wn[j], p);
        }
    }

    // warp reduce (4 warps)
    #pragma unroll
    for (int off = 16; off > 0; off >>= 1)
        p += __shfl_down_sync(0xffffffffu, p, off);
    if ((tid & 31) == 0) s_red[tid >> 5] = p;
    __syncthreads();

    if (tid < (GTH_THREADS / 32)) {
        float q = s_red[tid];
        #pragma unroll
        for (int off = (GTH_THREADS / 64); off > 0; off >>= 1)
            q += __shfl_down_sync(0xfu, q, off);
        if (tid == 0) {
            float x = q + b_out[0];
            out[b] = 1.0f / (1.0f + expf(-x));
        }
    }
}

extern "C" void kernel_launch(void* const* d_in, const int* in_sizes, int n_in,
                              void* d_out, int out_size) {
    // metadata order:
    // 0 values, 1 stm_feat, 2 nstm_feat, 3 batch_idx, 4 W_ft, 5 b_ft,
    // 6 W_fft, 7 b_fft, 8 W_out, 9 b_out, 10 size
    const float* values    = (const float*)d_in[0];
    const int*   stm_feat  = (const int*)d_in[1];
    const int*   nstm_feat = (const int*)d_in[2];
    const float* W_ft      = (const float*)d_in[4];
    const float* b_ft      = (const float*)d_in[5];
    const float* W_fft     = (const float*)d_in[6];
    const float* b_fft     = (const float*)d_in[7];
    const float* W_out     = (const float*)d_in[8];
    const float* b_out     = (const float*)d_in[9];
    float* out = (float*)d_out;

    const int B = out_size;  // 8192

    build_comb_kernel<<<NFEAT / 8, BLD_THREADS>>>(W_ft, W_fft);

    // Gather launched with Programmatic Stream Serialization: it may begin
    // launching while build's tail CTAs run; griddepcontrol.wait inside the
    // kernel enforces the data dependency.
    {
        cudaLaunchConfig_t cfg = {};
        cfg.gridDim  = dim3(B, 1, 1);
        cfg.blockDim = dim3(GTH_THREADS, 1, 1);
        cfg.dynamicSmemBytes = 0;
        cfg.stream = 0;
        cudaLaunchAttribute attr[1];
        attr[0].id = cudaLaunchAttributeProgrammaticStreamSerialization;
        attr[0].val.programmaticStreamSerializationAllowed = 1;
        cfg.attrs = attr;
        cfg.numAttrs = 1;
        cudaLaunchKernelEx(&cfg, nnue_gather_kernel,
                           values, stm_feat, nstm_feat,
                           b_ft, b_fft, W_out, b_out, out);
    }
}